// round 3
// baseline (speedup 1.0000x reference)
#include <cuda_runtime.h>

#define NV 500000
#define CC 8
#define KK 27

typedef unsigned long long u64;

// Ping-pong intermediates for both grids: [2N, 8] each.
__device__ float g_t1[2 * NV * CC];
__device__ float g_t2[2 * NV * CC];
// Transposed neighbor maps: [grid][tap][voxel].
__device__ int g_nbrt[2][KK * NV];
// Packed f32x2 weights: [layer][grid][k][cp][d], cp = channel-pair (2cp,2cp+1).
__device__ u64 g_w2[3 * 2 * KK * 32];

// fma.rn.f32x2 : acc = a*b + acc, elementwise on packed fp32 pairs.
#define FMA2(acc, a, b) \
    asm("fma.rn.f32x2 %0, %1, %2, %0;" : "+l"(acc) : "l"(a), "l"(b))
#define ADD2(acc, o) \
    asm("add.rn.f32x2 %0, %0, %1;" : "+l"(acc) : "l"(o))
#define UNPACK2(lo, hi, v) \
    asm("mov.b64 {%0, %1}, %2;" : "=f"(lo), "=f"(hi) : "l"(v))

// ---------------------------------------------------------------------------
// Transpose [N,27] neighbor map into tap-major [27,N]. NV % 32 == 0.
// ---------------------------------------------------------------------------
__global__ void __launch_bounds__(256)
nbr_transpose_kernel(const int* __restrict__ nbr0, const int* __restrict__ nbr1)
{
    __shared__ int tile[32][29];
    const int g = blockIdx.y;
    const int* __restrict__ src = g ? nbr1 : nbr0;
    const int base = blockIdx.x * 32;

    for (int t = threadIdx.x; t < 32 * KK; t += blockDim.x)
        tile[t / KK][t % KK] = src[(size_t)base * KK + t];
    __syncthreads();

    int* __restrict__ dst = g_nbrt[g];
    for (int t = threadIdx.x; t < 32 * KK; t += blockDim.x) {
        int k = t / 32, r = t % 32;
        dst[(size_t)k * NV + base + r] = tile[r][k];
    }
}

// ---------------------------------------------------------------------------
// Pack weights into f32x2 pairs over c: g_w2[((L*2+g)*27+k)*32 + cp*8 + d]
//   = { W[L][k][2cp][d], W[L][k][2cp+1][d] }
// ---------------------------------------------------------------------------
__global__ void weight_pack_kernel(const float* __restrict__ W0,
                                   const float* __restrict__ W1)
{
    int e = blockIdx.x * blockDim.x + threadIdx.x;
    if (e >= 3 * 2 * KK * 32) return;
    int d  = e & 7;
    int cp = (e >> 3) & 3;
    int k  = (e >> 5) % KK;
    int g  = (e / (32 * KK)) & 1;
    int L  = e / (32 * KK * 2);
    const float* W = (g ? W1 : W0) + (size_t)(L * KK + k) * 64;
    float lo = W[(2 * cp) * 8 + d];
    float hi = W[(2 * cp + 1) * 8 + d];
    u64 v;
    asm("mov.b64 %0, {%1, %2};" : "=l"(v) : "f"(lo), "f"(hi));
    g_w2[e] = v;
}

// ---------------------------------------------------------------------------
// One layer, pair-lane: 2 threads per voxel (h = input-channel half),
// f32x2 packed FMAs, tap-major nbr, f32x2 weights in smem.
// ---------------------------------------------------------------------------
template <int LAYER>
__global__ void __launch_bounds__(320)
sconv2_kernel(const float* __restrict__ feats0, const float* __restrict__ feats1,
              float* __restrict__ out)
{
    __shared__ u64 s_w[2 * KK * 32];  // 13824 B: this layer, both grids
    for (int e = threadIdx.x; e < 2 * KK * 32; e += 320)
        s_w[e] = g_w2[LAYER * 2 * KK * 32 + e];
    __syncthreads();

    const long long t = (long long)blockIdx.x * 320 + threadIdx.x;  // 2M exact
    const int h = (int)(t & 1);
    const int p = (int)(t >> 1);        // voxel slot 0..2N-1 (uniform g per warp)
    const int g = (p >= NV) ? 1 : 0;
    const int i = g ? p - NV : p;

    const float* xin;
    if (LAYER == 0)      xin = g ? feats1 : feats0;
    else if (LAYER == 1) xin = g_t1 + (size_t)g * NV * CC;
    else                 xin = g_t2 + (size_t)g * NV * CC;

    const int* __restrict__ nb = &g_nbrt[g][i];
    const u64* __restrict__ wb = s_w + (size_t)g * (KK * 32) + h * 16;

    u64 acc[8];
#pragma unroll
    for (int d = 0; d < 8; d++) acc[d] = 0ull;  // (0.0f, 0.0f)

#pragma unroll
    for (int k = 0; k < KK; k++) {
        int idx = nb[k * NV];
        ulonglong2 xv;
        if (idx >= 0) {
            xv = *(const ulonglong2*)(xin + (size_t)idx * CC + h * 4);
        } else {
            xv.x = 0ull; xv.y = 0ull;
        }
        const ulonglong2* wp = (const ulonglong2*)(wb + k * 32);
#pragma unroll
        for (int j = 0; j < 4; j++) {
            ulonglong2 w = wp[j];          // cp = 2h, d = 2j, 2j+1
            FMA2(acc[2 * j],     xv.x, w.x);
            FMA2(acc[2 * j + 1], xv.x, w.y);
        }
#pragma unroll
        for (int j = 0; j < 4; j++) {
            ulonglong2 w = wp[4 + j];      // cp = 2h+1
            FMA2(acc[2 * j],     xv.y, w.x);
            FMA2(acc[2 * j + 1], xv.y, w.y);
        }
    }

    // Combine the two input-channel halves (lane ^ 1), then fold f32x2 -> f32.
    float res[8];
#pragma unroll
    for (int d = 0; d < 8; d++) {
        u64 o = __shfl_xor_sync(0xffffffffu, acc[d], 1);
        ADD2(acc[d], o);
        float lo, hi;
        UNPACK2(lo, hi, acc[d]);
        res[d] = lo + hi;
    }

    const int d0 = 4 * h;  // this lane stores output channels d0..d0+3
    float4 o4;
    if (LAYER < 2) {
        o4 = make_float4(fmaxf(res[d0 + 0], 0.0f), fmaxf(res[d0 + 1], 0.0f),
                         fmaxf(res[d0 + 2], 0.0f), fmaxf(res[d0 + 3], 0.0f));
    } else {
        const float* fr = (g ? feats1 : feats0) + (size_t)i * CC + d0;
        float4 r = *(const float4*)fr;
        o4 = make_float4(res[d0 + 0] + r.x, res[d0 + 1] + r.y,
                         res[d0 + 2] + r.z, res[d0 + 3] + r.w);
    }

    float* op = (LAYER == 0) ? g_t1 : (LAYER == 1) ? g_t2 : out;
    *(float4*)(op + (size_t)p * CC + d0) = o4;
}

extern "C" void kernel_launch(void* const* d_in, const int* in_sizes, int n_in,
                              void* d_out, int out_size)
{
    const float* feats0 = (const float*)d_in[0];
    const float* feats1 = (const float*)d_in[1];
    const float* W0     = (const float*)d_in[2];
    const float* W1     = (const float*)d_in[3];
    const int*   nbr0   = (const int*)d_in[4];
    const int*   nbr1   = (const int*)d_in[5];
    float*       out    = (float*)d_out;

    {
        dim3 grid(NV / 32, 2);
        nbr_transpose_kernel<<<grid, 256>>>(nbr0, nbr1);
    }
    weight_pack_kernel<<<(3 * 2 * KK * 32 + 255) / 256, 256>>>(W0, W1);

    const int blocks = (2 * NV * 2) / 320;  // 2,000,000 threads exactly
    sconv2_kernel<0><<<blocks, 320>>>(feats0, feats1, out);
    sconv2_kernel<1><<<blocks, 320>>>(feats0, feats1, out);
    sconv2_kernel<2><<<blocks, 320>>>(feats0, feats1, out);
}

// round 4
// speedup vs baseline: 1.5932x; 1.5932x over previous
#include <cuda_runtime.h>

#define NV 500000
#define CC 8
#define KK 27

typedef unsigned long long u64;

// Ping-pong intermediates for both grids: [2N, 8] each.
__device__ float g_t1[2 * NV * CC];
__device__ float g_t2[2 * NV * CC];
// Transposed neighbor maps: [grid][tap][voxel].
__device__ int g_nbrt[2][KK * NV];

// Packed fp32-pair helpers.
#define FMA2(acc, a, b) \
    asm("fma.rn.f32x2 %0, %1, %2, %0;" : "+l"(acc) : "l"(a), "l"(b))
#define DUP2(dst, x) \
    asm("mov.b64 %0, {%1, %1};" : "=l"(dst) : "f"(x))
#define UNPACK2(lo, hi, v) \
    asm("mov.b64 {%0, %1}, %2;" : "=f"(lo), "=f"(hi) : "l"(v))

// 256-bit global load/store (Blackwell LDG.E.256 / STG.E.256). 32B-aligned.
__device__ __forceinline__ void ldg256(const float* __restrict__ p, float* x) {
    asm("ld.global.nc.v8.f32 {%0,%1,%2,%3,%4,%5,%6,%7}, [%8];"
        : "=f"(x[0]), "=f"(x[1]), "=f"(x[2]), "=f"(x[3]),
          "=f"(x[4]), "=f"(x[5]), "=f"(x[6]), "=f"(x[7])
        : "l"(p));
}
__device__ __forceinline__ void stg256(float* __restrict__ p, const float* x) {
    asm volatile("st.global.v8.f32 [%0], {%1,%2,%3,%4,%5,%6,%7,%8};"
        :: "l"(p),
           "f"(x[0]), "f"(x[1]), "f"(x[2]), "f"(x[3]),
           "f"(x[4]), "f"(x[5]), "f"(x[6]), "f"(x[7])
        : "memory");
}

// ---------------------------------------------------------------------------
// Transpose [N,27] neighbor map into tap-major [27,N]. NV % 32 == 0.
// ---------------------------------------------------------------------------
__global__ void __launch_bounds__(256)
nbr_transpose_kernel(const int* __restrict__ nbr0, const int* __restrict__ nbr1)
{
    __shared__ int tile[32][29];
    const int g = blockIdx.y;
    const int* __restrict__ src = g ? nbr1 : nbr0;
    const int base = blockIdx.x * 32;

    for (int t = threadIdx.x; t < 32 * KK; t += blockDim.x)
        tile[t / KK][t % KK] = src[(size_t)base * KK + t];
    __syncthreads();

    int* __restrict__ dst = g_nbrt[g];
    for (int t = threadIdx.x; t < 32 * KK; t += blockDim.x) {
        int k = t / 32, r = t % 32;
        dst[(size_t)k * NV + base + r] = tile[r][k];
    }
}

// ---------------------------------------------------------------------------
// One layer. blockIdx.y = grid. Each thread processes M=4 voxels so the
// per-tap weight LDS is amortized 4x. Accumulators are f32x2 pairs over the
// output-channel dimension (weights are contiguous in d -> direct u64 reads).
// LAYER 0: in = feats,  out = g_t1,  ReLU
// LAYER 1: in = g_t1,   out = g_t2,  ReLU
// LAYER 2: in = g_t2,   out = d_out, + residual(feats)
// ---------------------------------------------------------------------------
#define MV 4
#define TPB 256
#define VPB (MV * TPB)   // 1024 voxels per block

template <int LAYER>
__global__ void __launch_bounds__(TPB, 2)
sconv4_kernel(const float* __restrict__ feats0, const float* __restrict__ feats1,
              const float* __restrict__ W0, const float* __restrict__ W1,
              float* __restrict__ out)
{
    const int g = blockIdx.y;

    // This layer's + this grid's weights: 27*64 floats, d contiguous.
    __shared__ __align__(16) float s_w[KK * CC * CC];
    {
        const float* w = (g ? W1 : W0) + (size_t)LAYER * KK * CC * CC;
        for (int t = threadIdx.x; t < KK * CC * CC; t += TPB)
            s_w[t] = w[t];
    }
    __syncthreads();

    const float* xin;
    if (LAYER == 0)      xin = g ? feats1 : feats0;
    else if (LAYER == 1) xin = g_t1 + (size_t)g * NV * CC;
    else                 xin = g_t2 + (size_t)g * NV * CC;

    const int base = blockIdx.x * VPB + threadIdx.x;
    int  iv[MV];
    bool valid[MV];
#pragma unroll
    for (int m = 0; m < MV; m++) {
        iv[m] = base + m * TPB;
        valid[m] = iv[m] < NV;
    }

    const int* __restrict__ nb = g_nbrt[g];

    u64 acc[MV][4];  // acc[m][j] = (out[2j], out[2j+1]) for voxel m
#pragma unroll
    for (int m = 0; m < MV; m++)
#pragma unroll
        for (int j = 0; j < 4; j++) acc[m][j] = 0ull;

#pragma unroll 1
    for (int k = 0; k < KK; k++) {
        int idx[MV];
#pragma unroll
        for (int m = 0; m < MV; m++)
            idx[m] = valid[m] ? nb[(size_t)k * NV + iv[m]] : -1;

        float xs[MV][CC];
#pragma unroll
        for (int m = 0; m < MV; m++) {
            if (idx[m] >= 0) {
                ldg256(xin + (size_t)idx[m] * CC, xs[m]);
            } else {
#pragma unroll
                for (int c = 0; c < CC; c++) xs[m][c] = 0.0f;
            }
        }

        const ulonglong2* __restrict__ wk =
            (const ulonglong2*)(s_w + k * CC * CC);
#pragma unroll
        for (int c = 0; c < CC; c++) {
            ulonglong2 w01 = wk[2 * c];      // (d0,d1),(d2,d3)
            ulonglong2 w23 = wk[2 * c + 1];  // (d4,d5),(d6,d7)
#pragma unroll
            for (int m = 0; m < MV; m++) {
                u64 xc;
                DUP2(xc, xs[m][c]);
                FMA2(acc[m][0], xc, w01.x);
                FMA2(acc[m][1], xc, w01.y);
                FMA2(acc[m][2], xc, w23.x);
                FMA2(acc[m][3], xc, w23.y);
            }
        }
    }

    float* op = (LAYER == 0) ? g_t1 : (LAYER == 1) ? g_t2 : out;
    const float* resid = g ? feats1 : feats0;

#pragma unroll
    for (int m = 0; m < MV; m++) {
        if (!valid[m]) continue;
        float r[CC];
#pragma unroll
        for (int j = 0; j < 4; j++)
            UNPACK2(r[2 * j], r[2 * j + 1], acc[m][j]);

        if (LAYER < 2) {
#pragma unroll
            for (int d = 0; d < CC; d++) r[d] = fmaxf(r[d], 0.0f);
        } else {
            float rr[CC];
            ldg256(resid + (size_t)iv[m] * CC, rr);
#pragma unroll
            for (int d = 0; d < CC; d++) r[d] += rr[d];
        }
        stg256(op + ((size_t)g * NV + iv[m]) * CC, r);
    }
}

extern "C" void kernel_launch(void* const* d_in, const int* in_sizes, int n_in,
                              void* d_out, int out_size)
{
    const float* feats0 = (const float*)d_in[0];
    const float* feats1 = (const float*)d_in[1];
    const float* W0     = (const float*)d_in[2];
    const float* W1     = (const float*)d_in[3];
    const int*   nbr0   = (const int*)d_in[4];
    const int*   nbr1   = (const int*)d_in[5];
    float*       out    = (float*)d_out;

    {
        dim3 grid(NV / 32, 2);
        nbr_transpose_kernel<<<grid, 256>>>(nbr0, nbr1);
    }

    dim3 grid((NV + VPB - 1) / VPB, 2);  // 489 x 2
    sconv4_kernel<0><<<grid, TPB>>>(feats0, feats1, W0, W1, out);
    sconv4_kernel<1><<<grid, TPB>>>(feats0, feats1, W0, W1, out);
    sconv4_kernel<2><<<grid, TPB>>>(feats0, feats1, W0, W1, out);
}

// round 5
// speedup vs baseline: 1.8933x; 1.1884x over previous
#include <cuda_runtime.h>

#define NV 500000
#define CC 8
#define KK 27

typedef unsigned long long u64;

// Ping-pong intermediates for both grids: [2N, 8] each.
__device__ float g_t1[2 * NV * CC];
__device__ float g_t2[2 * NV * CC];
// Transposed neighbor maps: [grid][tap][voxel].
__device__ int g_nbrt[2][KK * NV];
// c-pair packed weights: [layer][grid][k][cp][d] = (W[2cp][d], W[2cp+1][d]).
__device__ u64 g_w2[3 * 2 * KK * 32];

#define FMA2(acc, a, b) \
    asm("fma.rn.f32x2 %0, %1, %2, %0;" : "+l"(acc) : "l"(a), "l"(b))
#define PACK2(dst, lo, hi) \
    asm("mov.b64 %0, {%1, %2};" : "=l"(dst) : "f"(lo), "f"(hi))
#define UNPACK2(lo, hi, v) \
    asm("mov.b64 {%0, %1}, %2;" : "=f"(lo), "=f"(hi) : "l"(v))

__device__ __forceinline__ void ldg256(const float* __restrict__ p, float* x) {
    asm("ld.global.nc.v8.f32 {%0,%1,%2,%3,%4,%5,%6,%7}, [%8];"
        : "=f"(x[0]), "=f"(x[1]), "=f"(x[2]), "=f"(x[3]),
          "=f"(x[4]), "=f"(x[5]), "=f"(x[6]), "=f"(x[7])
        : "l"(p));
}
__device__ __forceinline__ void stg256(float* __restrict__ p, const float* x) {
    asm volatile("st.global.v8.f32 [%0], {%1,%2,%3,%4,%5,%6,%7,%8};"
        :: "l"(p),
           "f"(x[0]), "f"(x[1]), "f"(x[2]), "f"(x[3]),
           "f"(x[4]), "f"(x[5]), "f"(x[6]), "f"(x[7])
        : "memory");
}

// ---------------------------------------------------------------------------
// Transpose [N,27] neighbor map into tap-major [27,N]. NV % 32 == 0.
// ---------------------------------------------------------------------------
__global__ void __launch_bounds__(256)
nbr_transpose_kernel(const int* __restrict__ nbr0, const int* __restrict__ nbr1)
{
    __shared__ int tile[32][29];
    const int g = blockIdx.y;
    const int* __restrict__ src = g ? nbr1 : nbr0;
    const int base = blockIdx.x * 32;

    for (int t = threadIdx.x; t < 32 * KK; t += blockDim.x)
        tile[t / KK][t % KK] = src[(size_t)base * KK + t];
    __syncthreads();

    int* __restrict__ dst = g_nbrt[g];
    for (int t = threadIdx.x; t < 32 * KK; t += blockDim.x) {
        int k = t / 32, r = t % 32;
        dst[(size_t)k * NV + base + r] = tile[r][k];
    }
}

// ---------------------------------------------------------------------------
// Pack weights into c-pairs: g_w2[((L*2+g)*27+k)*32 + cp*8 + d]
//   = { W[L][k][2cp][d], W[L][k][2cp+1][d] }
// ---------------------------------------------------------------------------
__global__ void weight_pack_kernel(const float* __restrict__ W0,
                                   const float* __restrict__ W1)
{
    int e = blockIdx.x * blockDim.x + threadIdx.x;
    if (e >= 3 * 2 * KK * 32) return;
    int d  = e & 7;
    int cp = (e >> 3) & 3;
    int k  = (e >> 5) % KK;
    int g  = (e / (32 * KK)) & 1;
    int L  = e / (32 * KK * 2);
    const float* W = (g ? W1 : W0) + (size_t)(L * KK + k) * 64;
    u64 v;
    PACK2(v, W[(2 * cp) * 8 + d], W[(2 * cp + 1) * 8 + d]);
    g_w2[e] = v;
}

// ---------------------------------------------------------------------------
// One layer. blockIdx.y = grid, MV=2 voxels/thread.
// acc[m][d] = f32x2 (even-c partial, odd-c partial); fold at end.
// x c-pairs come straight from the 256-bit gather (no dup movs).
// Indices for tap k+1 prefetched during tap k.
// ---------------------------------------------------------------------------
#define MV 2
#define TPB 256
#define VPB (MV * TPB)   // 512 voxels per block

template <int LAYER>
__global__ void __launch_bounds__(TPB, 3)
sconv5_kernel(const float* __restrict__ feats0, const float* __restrict__ feats1,
              float* __restrict__ out)
{
    const int g = blockIdx.y;

    // This layer's + grid's packed weights: 27*32 u64 = 6912 B.
    __shared__ __align__(16) u64 s_w[KK * 32];
    for (int t = threadIdx.x; t < KK * 32; t += TPB)
        s_w[t] = g_w2[(size_t)(LAYER * 2 + g) * KK * 32 + t];
    __syncthreads();

    const float* xin;
    if (LAYER == 0)      xin = g ? feats1 : feats0;
    else if (LAYER == 1) xin = g_t1 + (size_t)g * NV * CC;
    else                 xin = g_t2 + (size_t)g * NV * CC;

    const int base = blockIdx.x * VPB + threadIdx.x;
    int  iv[MV];
    bool valid[MV];
#pragma unroll
    for (int m = 0; m < MV; m++) {
        iv[m] = base + m * TPB;
        valid[m] = iv[m] < NV;
    }

    const int* __restrict__ nb = g_nbrt[g];

    u64 acc[MV][CC];
#pragma unroll
    for (int m = 0; m < MV; m++)
#pragma unroll
        for (int d = 0; d < CC; d++) acc[m][d] = 0ull;

    // Prefetch tap-0 indices.
    int idx[MV];
#pragma unroll
    for (int m = 0; m < MV; m++)
        idx[m] = valid[m] ? __ldg(&nb[iv[m]]) : -1;

#pragma unroll 1
    for (int k = 0; k < KK; k++) {
        // Prefetch next tap's indices (clamped; tap 26 re-reads itself).
        const int kn = (k + 1 < KK) ? k + 1 : k;
        int nidx[MV];
#pragma unroll
        for (int m = 0; m < MV; m++)
            nidx[m] = valid[m] ? __ldg(&nb[(size_t)kn * NV + iv[m]]) : -1;

        // Gather this tap's rows as 4 c-pair u64s per voxel.
        u64 xv[MV][4];
#pragma unroll
        for (int m = 0; m < MV; m++) {
            if (idx[m] >= 0) {
                float x[8];
                ldg256(xin + (size_t)idx[m] * CC, x);
#pragma unroll
                for (int cp = 0; cp < 4; cp++)
                    PACK2(xv[m][cp], x[2 * cp], x[2 * cp + 1]);
            } else {
#pragma unroll
                for (int cp = 0; cp < 4; cp++) xv[m][cp] = 0ull;
            }
        }

        const ulonglong2* __restrict__ wk = (const ulonglong2*)(s_w + k * 32);
#pragma unroll
        for (int cp = 0; cp < 4; cp++) {
            ulonglong2 wa = wk[cp * 4 + 0];  // w2[cp][d0], w2[cp][d1]
            ulonglong2 wb = wk[cp * 4 + 1];
            ulonglong2 wc = wk[cp * 4 + 2];
            ulonglong2 wd = wk[cp * 4 + 3];
#pragma unroll
            for (int m = 0; m < MV; m++) {
                FMA2(acc[m][0], xv[m][cp], wa.x);
                FMA2(acc[m][1], xv[m][cp], wa.y);
                FMA2(acc[m][2], xv[m][cp], wb.x);
                FMA2(acc[m][3], xv[m][cp], wb.y);
                FMA2(acc[m][4], xv[m][cp], wc.x);
                FMA2(acc[m][5], xv[m][cp], wc.y);
                FMA2(acc[m][6], xv[m][cp], wd.x);
                FMA2(acc[m][7], xv[m][cp], wd.y);
            }
        }

#pragma unroll
        for (int m = 0; m < MV; m++) idx[m] = nidx[m];
    }

    float* op = (LAYER == 0) ? g_t1 : (LAYER == 1) ? g_t2 : out;
    const float* resid = g ? feats1 : feats0;

#pragma unroll
    for (int m = 0; m < MV; m++) {
        if (!valid[m]) continue;
        float r[CC];
#pragma unroll
        for (int d = 0; d < CC; d++) {
            float lo, hi;
            UNPACK2(lo, hi, acc[m][d]);
            r[d] = lo + hi;
        }
        if (LAYER < 2) {
#pragma unroll
            for (int d = 0; d < CC; d++) r[d] = fmaxf(r[d], 0.0f);
        } else {
            float rr[CC];
            ldg256(resid + (size_t)iv[m] * CC, rr);
#pragma unroll
            for (int d = 0; d < CC; d++) r[d] += rr[d];
        }
        stg256(op + ((size_t)g * NV + iv[m]) * CC, r);
    }
}

extern "C" void kernel_launch(void* const* d_in, const int* in_sizes, int n_in,
                              void* d_out, int out_size)
{
    const float* feats0 = (const float*)d_in[0];
    const float* feats1 = (const float*)d_in[1];
    const float* W0     = (const float*)d_in[2];
    const float* W1     = (const float*)d_in[3];
    const int*   nbr0   = (const int*)d_in[4];
    const int*   nbr1   = (const int*)d_in[5];
    float*       out    = (float*)d_out;

    {
        dim3 grid(NV / 32, 2);
        nbr_transpose_kernel<<<grid, 256>>>(nbr0, nbr1);
    }
    weight_pack_kernel<<<(3 * 2 * KK * 32 + 255) / 256, 256>>>(W0, W1);

    dim3 grid((NV + VPB - 1) / VPB, 2);  // 977 x 2
    sconv5_kernel<0><<<grid, TPB>>>(feats0, feats1, out);
    sconv5_kernel<1><<<grid, TPB>>>(feats0, feats1, out);
    sconv5_kernel<2><<<grid, TPB>>>(feats0, feats1, out);
}

// round 7
// speedup vs baseline: 2.2784x; 1.2034x over previous
#include <cuda_runtime.h>

#define NV 500000
#define CC 8
#define KK 27

typedef unsigned long long u64;

// Ping-pong intermediates for both grids: [2N, 8] each.
__device__ float g_t1[2 * NV * CC];
__device__ float g_t2[2 * NV * CC];
// Transposed neighbor maps: [grid][tap][voxel].
__device__ int g_nbrt[2][KK * NV];

// c-pair packed weights, ulonglong2 granules:
//   entry ((L*2+g)*27 + k)*16 + cp*4 + j  =
//     { (W[2cp][2j],W[2cp+1][2j]), (W[2cp][2j+1],W[2cp+1][2j+1]) }
#define WQ (3 * 2 * KK * 16)          // 2592 ulonglong2 = 41472 B
__device__   ulonglong2 g_wstage[WQ]; // staging (written by pack kernel)
__constant__ ulonglong2 c_w2[WQ];     // constant-bank copy (LDC port)

#define FMA2(acc, a, b) \
    asm("fma.rn.f32x2 %0, %1, %2, %0;" : "+l"(acc) : "l"(a), "l"(b))
#define PACK2(dst, lo, hi) \
    asm("mov.b64 %0, {%1, %2};" : "=l"(dst) : "f"(lo), "f"(hi))
#define UNPACK2(lo, hi, v) \
    asm("mov.b64 {%0, %1}, %2;" : "=f"(lo), "=f"(hi) : "l"(v))

__device__ __forceinline__ void ldg256(const float* __restrict__ p, float* x) {
    asm("ld.global.nc.v8.f32 {%0,%1,%2,%3,%4,%5,%6,%7}, [%8];"
        : "=f"(x[0]), "=f"(x[1]), "=f"(x[2]), "=f"(x[3]),
          "=f"(x[4]), "=f"(x[5]), "=f"(x[6]), "=f"(x[7])
        : "l"(p));
}
__device__ __forceinline__ void stg256(float* __restrict__ p, const float* x) {
    asm volatile("st.global.v8.f32 [%0], {%1,%2,%3,%4,%5,%6,%7,%8};"
        :: "l"(p),
           "f"(x[0]), "f"(x[1]), "f"(x[2]), "f"(x[3]),
           "f"(x[4]), "f"(x[5]), "f"(x[6]), "f"(x[7])
        : "memory");
}

// ---------------------------------------------------------------------------
// Transpose [N,27] neighbor map into tap-major [27,N]. NV % 32 == 0.
// ---------------------------------------------------------------------------
__global__ void __launch_bounds__(256)
nbr_transpose_kernel(const int* __restrict__ nbr0, const int* __restrict__ nbr1)
{
    __shared__ int tile[32][29];
    const int g = blockIdx.y;
    const int* __restrict__ src = g ? nbr1 : nbr0;
    const int base = blockIdx.x * 32;

    for (int t = threadIdx.x; t < 32 * KK; t += blockDim.x)
        tile[t / KK][t % KK] = src[(size_t)base * KK + t];
    __syncthreads();

    int* __restrict__ dst = g_nbrt[g];
    for (int t = threadIdx.x; t < 32 * KK; t += blockDim.x) {
        int k = t / 32, r = t % 32;
        dst[(size_t)k * NV + base + r] = tile[r][k];
    }
}

// ---------------------------------------------------------------------------
// Pack weights into c-pairs: u64 entry ((L*2+g)*27+k)*32 + cp*8 + d
//   = { W[L][k][2cp][d], W[L][k][2cp+1][d] }   (same as round-5 layout)
// ---------------------------------------------------------------------------
__global__ void weight_pack_kernel(const float* __restrict__ W0,
                                   const float* __restrict__ W1)
{
    int e = blockIdx.x * blockDim.x + threadIdx.x;
    if (e >= 3 * 2 * KK * 32) return;
    int d  = e & 7;
    int cp = (e >> 3) & 3;
    int k  = (e >> 5) % KK;
    int g  = (e / (32 * KK)) & 1;
    int L  = e / (32 * KK * 2);
    const float* W = (g ? W1 : W0) + (size_t)(L * KK + k) * 64;
    u64 v;
    PACK2(v, W[(2 * cp) * 8 + d], W[(2 * cp + 1) * 8 + d]);
    ((u64*)g_wstage)[e] = v;
}

// ---------------------------------------------------------------------------
// One layer. blockIdx.y = grid, MV=2 voxels/thread.
// acc[m][d] = f32x2 (even-c, odd-c partials); fold once at the end.
// Weights read from __constant__ (LDC/LDCU port) -> no L1 weight traffic.
// ---------------------------------------------------------------------------
#define MV 2
#define TPB 256
#define VPB (MV * TPB)

template <int LAYER>
__global__ void __launch_bounds__(TPB, 3)
sconv6_kernel(const float* __restrict__ feats0, const float* __restrict__ feats1,
              float* __restrict__ out)
{
    const int g = blockIdx.y;

    const float* xin;
    if (LAYER == 0)      xin = g ? feats1 : feats0;
    else if (LAYER == 1) xin = g_t1 + (size_t)g * NV * CC;
    else                 xin = g_t2 + (size_t)g * NV * CC;

    const int base = blockIdx.x * VPB + threadIdx.x;
    int  iv[MV];
    bool valid[MV];
#pragma unroll
    for (int m = 0; m < MV; m++) {
        iv[m] = base + m * TPB;
        valid[m] = iv[m] < NV;
    }

    const int* __restrict__ nb = g_nbrt[g];
    const int wbase = (LAYER * 2 + g) * KK * 16;  // ulonglong2 units

    u64 acc[MV][CC];
#pragma unroll
    for (int m = 0; m < MV; m++)
#pragma unroll
        for (int d = 0; d < CC; d++) acc[m][d] = 0ull;

    // Prefetch tap-0 indices.
    int idx[MV];
#pragma unroll
    for (int m = 0; m < MV; m++)
        idx[m] = valid[m] ? __ldg(&nb[iv[m]]) : -1;

#pragma unroll 1
    for (int k = 0; k < KK; k++) {
        const int kn = (k + 1 < KK) ? k + 1 : k;
        int nidx[MV];
#pragma unroll
        for (int m = 0; m < MV; m++)
            nidx[m] = valid[m] ? __ldg(&nb[(size_t)kn * NV + iv[m]]) : -1;

        u64 xv[MV][4];
#pragma unroll
        for (int m = 0; m < MV; m++) {
            if (idx[m] >= 0) {
                float x[8];
                ldg256(xin + (size_t)idx[m] * CC, x);
#pragma unroll
                for (int cp = 0; cp < 4; cp++)
                    PACK2(xv[m][cp], x[2 * cp], x[2 * cp + 1]);
            } else {
#pragma unroll
                for (int cp = 0; cp < 4; cp++) xv[m][cp] = 0ull;
            }
        }

        const int wk = wbase + k * 16;
#pragma unroll
        for (int cp = 0; cp < 4; cp++) {
            ulonglong2 wa = c_w2[wk + cp * 4 + 0];
            ulonglong2 wb = c_w2[wk + cp * 4 + 1];
            ulonglong2 wc = c_w2[wk + cp * 4 + 2];
            ulonglong2 wd = c_w2[wk + cp * 4 + 3];
#pragma unroll
            for (int m = 0; m < MV; m++) {
                FMA2(acc[m][0], xv[m][cp], wa.x);
                FMA2(acc[m][1], xv[m][cp], wa.y);
                FMA2(acc[m][2], xv[m][cp], wb.x);
                FMA2(acc[m][3], xv[m][cp], wb.y);
                FMA2(acc[m][4], xv[m][cp], wc.x);
                FMA2(acc[m][5], xv[m][cp], wc.y);
                FMA2(acc[m][6], xv[m][cp], wd.x);
                FMA2(acc[m][7], xv[m][cp], wd.y);
            }
        }

#pragma unroll
        for (int m = 0; m < MV; m++) idx[m] = nidx[m];
    }

    float* op = (LAYER == 0) ? g_t1 : (LAYER == 1) ? g_t2 : out;
    const float* resid = g ? feats1 : feats0;

#pragma unroll
    for (int m = 0; m < MV; m++) {
        if (!valid[m]) continue;
        float r[CC];
#pragma unroll
        for (int d = 0; d < CC; d++) {
            float lo, hi;
            UNPACK2(lo, hi, acc[m][d]);
            r[d] = lo + hi;
        }
        if (LAYER < 2) {
#pragma unroll
            for (int d = 0; d < CC; d++) r[d] = fmaxf(r[d], 0.0f);
        } else {
            float rr[CC];
            ldg256(resid + (size_t)iv[m] * CC, rr);
#pragma unroll
            for (int d = 0; d < CC; d++) r[d] += rr[d];
        }
        stg256(op + ((size_t)g * NV + iv[m]) * CC, r);
    }
}

extern "C" void kernel_launch(void* const* d_in, const int* in_sizes, int n_in,
                              void* d_out, int out_size)
{
    const float* feats0 = (const float*)d_in[0];
    const float* feats1 = (const float*)d_in[1];
    const float* W0     = (const float*)d_in[2];
    const float* W1     = (const float*)d_in[3];
    const int*   nbr0   = (const int*)d_in[4];
    const int*   nbr1   = (const int*)d_in[5];
    float*       out    = (float*)d_out;

    {
        dim3 grid(NV / 32, 2);
        nbr_transpose_kernel<<<grid, 256>>>(nbr0, nbr1);
    }
    weight_pack_kernel<<<(3 * 2 * KK * 32 + 255) / 256, 256>>>(W0, W1);

    // Stage packed weights into the constant bank (D2D async, capturable).
    void* stage_ptr = nullptr;
    cudaGetSymbolAddress(&stage_ptr, g_wstage);
    cudaMemcpyToSymbolAsync(c_w2, stage_ptr, sizeof(ulonglong2) * WQ, 0,
                            cudaMemcpyDeviceToDevice);

    dim3 grid((NV + VPB - 1) / VPB, 2);  // 977 x 2
    sconv6_kernel<0><<<grid, TPB>>>(feats0, feats1, out);
    sconv6_kernel<1><<<grid, TPB>>>(feats0, feats1, out);
    sconv6_kernel<2><<<grid, TPB>>>(feats0, feats1, out);
}

// round 8
// speedup vs baseline: 2.2924x; 1.0061x over previous
#include <cuda_runtime.h>

#define NV 500000
#define NVP1 (NV + 1)         // +1 zero row per grid
#define NV_PAD 500224         // = 977 * 512, exact layer-grid multiple
#define CC 8
#define KK 27

typedef unsigned long long u64;

// Padded inputs/intermediates, one zero row (index NV) per grid.
// Device globals are zero-initialized; row NV is never written -> stays 0.
__device__ float g_x [2 * NVP1 * CC];   // padded copy of feats
__device__ float g_t1[2 * NVP1 * CC];
__device__ float g_t2[2 * NVP1 * CC];
// Tap-major neighbor map, padded; invalid/pad entries remapped to NV.
__device__ int g_nbrt[2 * KK * NV_PAD];

// c-pair packed weights, ulonglong2 granules (d-pairs of c-pairs).
#define WQ (3 * 2 * KK * 16)
__device__   ulonglong2 g_wstage[WQ];
__constant__ ulonglong2 c_w2[WQ];

#define FMA2(acc, a, b) \
    asm("fma.rn.f32x2 %0, %1, %2, %0;" : "+l"(acc) : "l"(a), "l"(b))
#define PACK2(dst, lo, hi) \
    asm("mov.b64 %0, {%1, %2};" : "=l"(dst) : "f"(lo), "f"(hi))
#define UNPACK2(lo, hi, v) \
    asm("mov.b64 {%0, %1}, %2;" : "=f"(lo), "=f"(hi) : "l"(v))

// 256-bit loads/stores (Blackwell). Rows are 32B and 32B-aligned.
__device__ __forceinline__ void ldg256_u64(const float* __restrict__ p, u64* x) {
    asm("ld.global.nc.v4.b64 {%0,%1,%2,%3}, [%4];"
        : "=l"(x[0]), "=l"(x[1]), "=l"(x[2]), "=l"(x[3]) : "l"(p));
}
__device__ __forceinline__ void ldg256(const float* __restrict__ p, float* x) {
    asm("ld.global.nc.v8.f32 {%0,%1,%2,%3,%4,%5,%6,%7}, [%8];"
        : "=f"(x[0]), "=f"(x[1]), "=f"(x[2]), "=f"(x[3]),
          "=f"(x[4]), "=f"(x[5]), "=f"(x[6]), "=f"(x[7])
        : "l"(p));
}
__device__ __forceinline__ void stg256(float* __restrict__ p, const float* x) {
    asm volatile("st.global.v8.f32 [%0], {%1,%2,%3,%4,%5,%6,%7,%8};"
        :: "l"(p),
           "f"(x[0]), "f"(x[1]), "f"(x[2]), "f"(x[3]),
           "f"(x[4]), "f"(x[5]), "f"(x[6]), "f"(x[7])
        : "memory");
}

// ---------------------------------------------------------------------------
// Transpose [N,27] -> tap-major [27,NV_PAD]; -1 and pad rows -> NV (zero row).
// ---------------------------------------------------------------------------
__global__ void __launch_bounds__(256)
nbr_transpose_kernel(const int* __restrict__ nbr0, const int* __restrict__ nbr1)
{
    __shared__ int tile[32][29];
    const int g = blockIdx.y;
    const int base = blockIdx.x * 32;
    int* __restrict__ dst = g_nbrt + (size_t)g * KK * NV_PAD;

    if (base >= NV) {  // pad block (NV % 32 == 0, so blocks are all-pad or all-real)
        for (int t = threadIdx.x; t < 32 * KK; t += blockDim.x)
            dst[(size_t)(t / 32) * NV_PAD + base + (t % 32)] = NV;
        return;
    }

    const int* __restrict__ src = g ? nbr1 : nbr0;
    for (int t = threadIdx.x; t < 32 * KK; t += blockDim.x)
        tile[t / KK][t % KK] = src[(size_t)base * KK + t];
    __syncthreads();

    for (int t = threadIdx.x; t < 32 * KK; t += blockDim.x) {
        int k = t / 32, r = t % 32;
        int v = tile[r][k];
        dst[(size_t)k * NV_PAD + base + r] = (v < 0) ? NV : v;
    }
}

// ---------------------------------------------------------------------------
// Copy feats into padded buffers (row NV stays zero).
// ---------------------------------------------------------------------------
__global__ void __launch_bounds__(256)
feats_copy_kernel(const float* __restrict__ f0, const float* __restrict__ f1)
{
    int t = blockIdx.x * blockDim.x + threadIdx.x;
    if (t >= 2 * NV) return;
    int g = (t >= NV) ? 1 : 0;
    int i = g ? t - NV : t;
    float x[8];
    ldg256((g ? f1 : f0) + (size_t)i * CC, x);
    stg256(g_x + ((size_t)g * NVP1 + i) * CC, x);
}

// ---------------------------------------------------------------------------
// Pack weights into c-pairs: u64 entry ((L*2+g)*27+k)*32 + cp*8 + d
//   = { W[L][k][2cp][d], W[L][k][2cp+1][d] }
// ---------------------------------------------------------------------------
__global__ void weight_pack_kernel(const float* __restrict__ W0,
                                   const float* __restrict__ W1)
{
    int e = blockIdx.x * blockDim.x + threadIdx.x;
    if (e >= 3 * 2 * KK * 32) return;
    int d  = e & 7;
    int cp = (e >> 3) & 3;
    int k  = (e >> 5) % KK;
    int g  = (e / (32 * KK)) & 1;
    int L  = e / (32 * KK * 2);
    const float* W = (g ? W1 : W0) + (size_t)(L * KK + k) * 64;
    u64 v;
    PACK2(v, W[(2 * cp) * 8 + d], W[(2 * cp + 1) * 8 + d]);
    ((u64*)g_wstage)[e] = v;
}

// ---------------------------------------------------------------------------
// One layer: branch-free mainloop. blockIdx.y = grid, 2 voxels/thread.
// Gathers are unconditional 256-bit loads (invalid taps hit the zero row),
// loaded directly as u64 c-pairs. Weights via constant bank.
// ---------------------------------------------------------------------------
#define TPB 256
#define VPB (2 * TPB)   // 512

template <int LAYER>
__global__ void __launch_bounds__(TPB, 4)
sconv8_kernel(float* __restrict__ out)
{
    const int g = blockIdx.y;

    const float* xin;
    if (LAYER == 0)      xin = g_x  + (size_t)g * NVP1 * CC;
    else if (LAYER == 1) xin = g_t1 + (size_t)g * NVP1 * CC;
    else                 xin = g_t2 + (size_t)g * NVP1 * CC;

    const int iv0 = blockIdx.x * VPB + threadIdx.x;
    const int iv1 = iv0 + TPB;

    const int* __restrict__ nb = g_nbrt + (size_t)g * KK * NV_PAD;
    const int wbase = (LAYER * 2 + g) * KK * 16;

    u64 acc0[CC], acc1[CC];
#pragma unroll
    for (int d = 0; d < CC; d++) { acc0[d] = 0ull; acc1[d] = 0ull; }

    int idx0 = nb[iv0];
    int idx1 = nb[iv1];

#pragma unroll 1
    for (int k = 0; k < KK; k++) {
        const int kn = (k + 1 < KK) ? k + 1 : k;
        int n0 = nb[(size_t)kn * NV_PAD + iv0];
        int n1 = nb[(size_t)kn * NV_PAD + iv1];

        u64 xv0[4], xv1[4];
        ldg256_u64(xin + (size_t)idx0 * CC, xv0);
        ldg256_u64(xin + (size_t)idx1 * CC, xv1);

        const int wk = wbase + k * 16;
#pragma unroll
        for (int cp = 0; cp < 4; cp++) {
            ulonglong2 wa = c_w2[wk + cp * 4 + 0];
            ulonglong2 wb = c_w2[wk + cp * 4 + 1];
            ulonglong2 wc = c_w2[wk + cp * 4 + 2];
            ulonglong2 wd = c_w2[wk + cp * 4 + 3];
            FMA2(acc0[0], xv0[cp], wa.x);  FMA2(acc1[0], xv1[cp], wa.x);
            FMA2(acc0[1], xv0[cp], wa.y);  FMA2(acc1[1], xv1[cp], wa.y);
            FMA2(acc0[2], xv0[cp], wb.x);  FMA2(acc1[2], xv1[cp], wb.x);
            FMA2(acc0[3], xv0[cp], wb.y);  FMA2(acc1[3], xv1[cp], wb.y);
            FMA2(acc0[4], xv0[cp], wc.x);  FMA2(acc1[4], xv1[cp], wc.x);
            FMA2(acc0[5], xv0[cp], wc.y);  FMA2(acc1[5], xv1[cp], wc.y);
            FMA2(acc0[6], xv0[cp], wd.x);  FMA2(acc1[6], xv1[cp], wd.x);
            FMA2(acc0[7], xv0[cp], wd.y);  FMA2(acc1[7], xv1[cp], wd.y);
        }
        idx0 = n0; idx1 = n1;
    }

    const float* resid = g_x + (size_t)g * NVP1 * CC;

#pragma unroll
    for (int m = 0; m < 2; m++) {
        const int iv = m ? iv1 : iv0;
        if (iv >= NV) continue;
        const u64* acc = m ? acc1 : acc0;
        float r[CC];
#pragma unroll
        for (int d = 0; d < CC; d++) {
            float lo, hi;
            UNPACK2(lo, hi, acc[d]);
            r[d] = lo + hi;
        }
        if (LAYER < 2) {
#pragma unroll
            for (int d = 0; d < CC; d++) r[d] = fmaxf(r[d], 0.0f);
            float* op = (LAYER == 0) ? g_t1 : g_t2;
            stg256(op + ((size_t)g * NVP1 + iv) * CC, r);
        } else {
            float rr[CC];
            ldg256(resid + (size_t)iv * CC, rr);
#pragma unroll
            for (int d = 0; d < CC; d++) r[d] += rr[d];
            stg256(out + ((size_t)g * NV + iv) * CC, r);
        }
    }
}

extern "C" void kernel_launch(void* const* d_in, const int* in_sizes, int n_in,
                              void* d_out, int out_size)
{
    const float* feats0 = (const float*)d_in[0];
    const float* feats1 = (const float*)d_in[1];
    const float* W0     = (const float*)d_in[2];
    const float* W1     = (const float*)d_in[3];
    const int*   nbr0   = (const int*)d_in[4];
    const int*   nbr1   = (const int*)d_in[5];
    float*       out    = (float*)d_out;

    {
        dim3 grid(NV_PAD / 32, 2);  // 15632 x 2
        nbr_transpose_kernel<<<grid, 256>>>(nbr0, nbr1);
    }
    feats_copy_kernel<<<(2 * NV + 255) / 256, 256>>>(feats0, feats1);
    weight_pack_kernel<<<(3 * 2 * KK * 32 + 255) / 256, 256>>>(W0, W1);

    void* stage_ptr = nullptr;
    cudaGetSymbolAddress(&stage_ptr, g_wstage);
    cudaMemcpyToSymbolAsync(c_w2, stage_ptr, sizeof(ulonglong2) * WQ, 0,
                            cudaMemcpyDeviceToDevice);

    dim3 grid(NV_PAD / VPB, 2);  // 977 x 2
    sconv8_kernel<0><<<grid, TPB>>>(out);
    sconv8_kernel<1><<<grid, TPB>>>(out);
    sconv8_kernel<2><<<grid, TPB>>>(out);
}